// round 13
// baseline (speedup 1.0000x reference)
#include <cuda_runtime.h>
#include <stdint.h>

// MoE EP-combine: out[token_indices[r]] += sorted_gates[r] * expert_outputs[r]
// Inputs (metadata order):
//   d_in[0] output_buffer  f32 [16384, 2048]  (zeros; ignored)
//   d_in[1] expert_outputs f32 [32768, 2048]
//   d_in[2] sorted_gates   f32 [32768]
//   d_in[3] token_indices  (i32 or i64, runtime-detected) [32768]
// Output: f32 [16384, 2048]
//
// Self-cleaning counters: combine_kernel resets g_cnt[t] to 0 after use, so
// no zeroing pass is needed (globals are zero-init at module load; every
// graph replay leaves cnt back at 0).

#define NUM_TOKENS 16384
#define NUM_SEL    32768
#define D_MODEL    2048
#define D_VEC4     (D_MODEL / 4)      // 512 float4 per row
#define MAX_CONTRIB 32

__device__ int   g_cnt[NUM_TOKENS];
__device__ int   g_rows[NUM_TOKENS * MAX_CONTRIB];
__device__ float g_gate[NUM_TOKENS * MAX_CONTRIB];

// Index-dtype probe: if the buffer is genuine int64, every 8-byte word is a
// token id < NUM_TOKENS. If int32, the high 32 bits of a word hold another
// random token id, so >= NUM_TOKENS over 8 samples with prob ~1.
__device__ __forceinline__ int probe_idx_is_i64(const unsigned long long* p) {
    int is64 = 1;
    #pragma unroll
    for (int k = 0; k < 8; ++k)
        if (p[k] >= (unsigned long long)NUM_TOKENS) is64 = 0;
    return is64;
}

__global__ void __launch_bounds__(256) scatter_kernel(
    const void* __restrict__ token_indices,
    const float* __restrict__ gates)
{
    __shared__ int s_is64;
    if (threadIdx.x == 0)
        s_is64 = probe_idx_is_i64((const unsigned long long*)token_indices);
    __syncthreads();

    int r = blockIdx.x * blockDim.x + threadIdx.x;
    if (r >= NUM_SEL) return;

    int t;
    if (s_is64) t = (int)((const long long*)token_indices)[r];
    else        t = ((const int*)token_indices)[r];

    float g = gates[r];
    int slot = atomicAdd(&g_cnt[t], 1);
    if (slot < MAX_CONTRIB) {
        g_rows[t * MAX_CONTRIB + slot] = r;
        g_gate[t * MAX_CONTRIB + slot] = g;
    }
}

__device__ __forceinline__ void fma4(float4& a, float g, const float4& v) {
    a.x += g * v.x; a.y += g * v.y; a.z += g * v.z; a.w += g * v.w;
}

// One CTA (512 threads) per token. Each thread owns ONE float4 slot (16 B).
// Thin threads -> low register count -> 4 CTAs (64 warps) resident per SM,
// maximizing warps available to hide the metadata->expert load chain.
// Metadata (cnt, rows[0..3], gates[0..3]) is fetched with independent
// vectorized loads; slots beyond cnt are predicated off before any expert
// dereference (no wasted bandwidth).
__global__ void __launch_bounds__(512, 4) combine_kernel(
    const float4* __restrict__ expert,   // [NUM_SEL, D_VEC4]
    float4* __restrict__ out)            // [NUM_TOKENS, D_VEC4]
{
    const int t    = blockIdx.x;
    const int base = t * MAX_CONTRIB;
    const int i    = threadIdx.x;        // float4 index 0..511

    // Independent metadata loads (issue together):
    int    c      = g_cnt[t];
    int4   rows4  = *(const int4*)  (g_rows + base);   // slots 0..3
    float4 gates4 = *(const float4*)(g_gate + base);
    if (c > MAX_CONTRIB) c = MAX_CONTRIB;

    float4 acc = make_float4(0.f, 0.f, 0.f, 0.f);

    // Contributors 0..3 (c avg = 2; c <= 4 covers ~95% of tokens)
    if (c > 0) {
        float4 v0 = __ldcs(expert + (size_t)rows4.x * D_VEC4 + i);
        if (c > 1) {
            float4 v1 = __ldcs(expert + (size_t)rows4.y * D_VEC4 + i);
            if (c > 2) {
                float4 v2 = __ldcs(expert + (size_t)rows4.z * D_VEC4 + i);
                if (c > 3) {
                    float4 v3 = __ldcs(expert + (size_t)rows4.w * D_VEC4 + i);
                    fma4(acc, gates4.w, v3);
                }
                fma4(acc, gates4.z, v2);
            }
            fma4(acc, gates4.y, v1);
        }
        fma4(acc, gates4.x, v0);
    }

    // Rare tail: c > 4
    for (int j = 4; j < c; ++j) {
        int   r = g_rows[base + j];
        float g = g_gate[base + j];
        float4 v = __ldcs(expert + (size_t)r * D_VEC4 + i);
        fma4(acc, g, v);
    }

    // Self-clean the counter for the next launch / graph replay.
    if (threadIdx.x == 0) g_cnt[t] = 0;

    __stcs(out + (size_t)t * D_VEC4 + i, acc);
}

extern "C" void kernel_launch(void* const* d_in, const int* in_sizes, int n_in,
                              void* d_out, int out_size)
{
    const float* expert = (const float*)d_in[1];
    const float* gates  = (const float*)d_in[2];
    const void*  tidx   = d_in[3];
    float*       out    = (float*)d_out;

    scatter_kernel<<<(NUM_SEL + 255) / 256, 256>>>(tidx, gates);
    combine_kernel<<<NUM_TOKENS, 512>>>((const float4*)expert, (float4*)out);
}

// round 15
// speedup vs baseline: 1.0320x; 1.0320x over previous
#include <cuda_runtime.h>
#include <stdint.h>

// MoE EP-combine: out[token_indices[r]] += sorted_gates[r] * expert_outputs[r]
// Inputs (metadata order):
//   d_in[0] output_buffer  f32 [16384, 2048]  (zeros; ignored)
//   d_in[1] expert_outputs f32 [32768, 2048]
//   d_in[2] sorted_gates   f32 [32768]
//   d_in[3] token_indices  (i32 or i64, runtime-detected) [32768]
// Output: f32 [16384, 2048]
//
// Self-cleaning counters: combine_kernel resets g_cnt to 0 after use, so no
// zeroing pass is needed (globals zero-init at module load; every graph
// replay leaves cnt back at 0). Scatter is identical every replay, so slot
// contents are deterministic; slots never written stay 0 (row 0 / gate 0.0).

#define NUM_TOKENS 16384
#define NUM_SEL    32768
#define D_MODEL    2048
#define D_VEC4     (D_MODEL / 4)      // 512 float4 per row
#define MAX_CONTRIB 32

__device__ int   g_cnt[NUM_TOKENS];
__device__ int   g_rows[NUM_TOKENS * MAX_CONTRIB];
__device__ float g_gate[NUM_TOKENS * MAX_CONTRIB];

// Index-dtype probe: if the buffer is genuine int64, every 8-byte word is a
// token id < NUM_TOKENS. If int32, the high 32 bits of a word hold another
// random token id, so >= NUM_TOKENS over 8 samples with prob ~1.
__device__ __forceinline__ int probe_idx_is_i64(const unsigned long long* p) {
    int is64 = 1;
    #pragma unroll
    for (int k = 0; k < 8; ++k)
        if (p[k] >= (unsigned long long)NUM_TOKENS) is64 = 0;
    return is64;
}

__global__ void __launch_bounds__(256) scatter_kernel(
    const void* __restrict__ token_indices,
    const float* __restrict__ gates)
{
    __shared__ int s_is64;
    if (threadIdx.x == 0)
        s_is64 = probe_idx_is_i64((const unsigned long long*)token_indices);
    __syncthreads();

    int r = blockIdx.x * blockDim.x + threadIdx.x;
    if (r >= NUM_SEL) return;

    int t;
    if (s_is64) t = (int)((const long long*)token_indices)[r];
    else        t = ((const int*)token_indices)[r];

    float g = gates[r];
    int slot = atomicAdd(&g_cnt[t], 1);
    if (slot < MAX_CONTRIB) {
        g_rows[t * MAX_CONTRIB + slot] = r;
        g_gate[t * MAX_CONTRIB + slot] = g;
    }
}

__device__ __forceinline__ void fma4(float4& a, float g, const float4& v) {
    a.x += g * v.x; a.y += g * v.y; a.z += g * v.z; a.w += g * v.w;
}
__device__ __forceinline__ float4 zero4() { return make_float4(0.f,0.f,0.f,0.f); }

// One CTA (256 threads) per TWO tokens. Each thread owns 2 float4 slots of
// each token. At c=2 per token that is 8 independent 16B expert loads in
// flight per thread, all issued at CTA top. Contributor loads are
// single-statement predicated (@P LDG, no branch sync) into zero-initialized
// registers; FMAs are unconditional (gate slots beyond cnt are 0.0 or a
// deterministic replay value multiplying a zero vector).
__global__ void __launch_bounds__(256) combine_kernel(
    const float4* __restrict__ expert,   // [NUM_SEL, D_VEC4]
    float4* __restrict__ out)            // [NUM_TOKENS, D_VEC4]
{
    const int t0 = blockIdx.x * 2;
    const int t1 = t0 + 1;
    const int b0 = t0 * MAX_CONTRIB;
    const int b1 = t1 * MAX_CONTRIB;

    // Independent metadata loads (all issue together):
    int    c0 = g_cnt[t0];
    int    c1 = g_cnt[t1];
    int4   rA = *(const int4*)  (g_rows + b0);
    int4   rB = *(const int4*)  (g_rows + b1);
    float4 gA = *(const float4*)(g_gate + b0);
    float4 gB = *(const float4*)(g_gate + b1);
    if (c0 > MAX_CONTRIB) c0 = MAX_CONTRIB;
    if (c1 > MAX_CONTRIB) c1 = MAX_CONTRIB;

    const int i0 = threadIdx.x;          // float4 index 0..255
    const int i1 = threadIdx.x + 256;    // float4 index 256..511

    // Predicated contributor loads, contributors 0..1 of each token (c avg=2)
    float4 a00 = zero4(), a01 = zero4();   // token0 slot0/slot1 accumulators
    float4 a10 = zero4(), a11 = zero4();   // token1

    float4 vA00 = zero4(), vA01 = zero4(), vA10 = zero4(), vA11 = zero4();
    float4 vB00 = zero4(), vB01 = zero4(), vB10 = zero4(), vB11 = zero4();

    const float4* eA0 = expert + (size_t)rA.x * D_VEC4;
    const float4* eA1 = expert + (size_t)rA.y * D_VEC4;
    const float4* eB0 = expert + (size_t)rB.x * D_VEC4;
    const float4* eB1 = expert + (size_t)rB.y * D_VEC4;

    if (c0 > 0) vA00 = __ldcs(eA0 + i0);
    if (c0 > 0) vA01 = __ldcs(eA0 + i1);
    if (c0 > 1) vA10 = __ldcs(eA1 + i0);
    if (c0 > 1) vA11 = __ldcs(eA1 + i1);
    if (c1 > 0) vB00 = __ldcs(eB0 + i0);
    if (c1 > 0) vB01 = __ldcs(eB0 + i1);
    if (c1 > 1) vB10 = __ldcs(eB1 + i0);
    if (c1 > 1) vB11 = __ldcs(eB1 + i1);

    fma4(a00, gA.x, vA00); fma4(a01, gA.x, vA01);
    fma4(a00, gA.y, vA10); fma4(a01, gA.y, vA11);
    fma4(a10, gB.x, vB00); fma4(a11, gB.x, vB01);
    fma4(a10, gB.y, vB10); fma4(a11, gB.y, vB11);

    // Tail: contributors 2.. (P(c>2) ~ 32% per token under Poisson(2))
    for (int j = 2; j < c0; ++j) {
        int   r = g_rows[b0 + j];
        float g = g_gate[b0 + j];
        const float4* e = expert + (size_t)r * D_VEC4;
        float4 v0 = __ldcs(e + i0), v1 = __ldcs(e + i1);
        fma4(a00, g, v0); fma4(a01, g, v1);
    }
    for (int j = 2; j < c1; ++j) {
        int   r = g_rows[b1 + j];
        float g = g_gate[b1 + j];
        const float4* e = expert + (size_t)r * D_VEC4;
        float4 v0 = __ldcs(e + i0), v1 = __ldcs(e + i1);
        fma4(a10, g, v0); fma4(a11, g, v1);
    }

    // Self-clean counters for the next launch / graph replay.
    if (threadIdx.x == 0) { g_cnt[t0] = 0; g_cnt[t1] = 0; }

    float4* o0 = out + (size_t)t0 * D_VEC4;
    float4* o1 = out + (size_t)t1 * D_VEC4;
    __stcs(o0 + i0, a00);
    __stcs(o0 + i1, a01);
    __stcs(o1 + i0, a10);
    __stcs(o1 + i1, a11);
}

extern "C" void kernel_launch(void* const* d_in, const int* in_sizes, int n_in,
                              void* d_out, int out_size)
{
    const float* expert = (const float*)d_in[1];
    const float* gates  = (const float*)d_in[2];
    const void*  tidx   = d_in[3];
    float*       out    = (float*)d_out;

    scatter_kernel<<<(NUM_SEL + 255) / 256, 256>>>(tidx, gates);
    combine_kernel<<<NUM_TOKENS / 2, 256>>>((const float4*)expert, (float4*)out);
}